// round 6
// baseline (speedup 1.0000x reference)
#include <cuda_runtime.h>
#include <math.h>

// Problem constants
#define BB 4
#define KKK 512          // slots per batch
#define DDD 512          // slot dim
#define DPP 128          // pairwise dim
#define NH 8             // heads
#define HDIM 64          // head dim
#define MROWS (BB*KKK)   // 2048
#define BH (BB*NH)       // 32

typedef unsigned long long u64;

// ---------- packed fp32x2 helpers (Blackwell FFMA2) ----------
__device__ __forceinline__ u64 dup2f(float x){
    u64 r; unsigned xi = __float_as_uint(x);
    asm("mov.b64 %0, {%1,%1};" : "=l"(r) : "r"(xi));
    return r;
}
__device__ __forceinline__ u64 pack2f(float x, float y){
    u64 r;
    asm("mov.b64 %0, {%1,%2};" : "=l"(r) : "r"(__float_as_uint(x)), "r"(__float_as_uint(y)));
    return r;
}
__device__ __forceinline__ void unpack2f(u64 v, float &x, float &y){
    unsigned a,b;
    asm("mov.b64 {%0,%1}, %2;" : "=r"(a), "=r"(b) : "l"(v));
    x = __uint_as_float(a); y = __uint_as_float(b);
}
__device__ __forceinline__ void ffma2(u64 &d, u64 a, u64 b){
    asm("fma.rn.f32x2 %0, %1, %2, %0;" : "+l"(d) : "l"(a), "l"(b));
}

// ---------- scratch (no dynamic allocation allowed) ----------
__device__ float g_x[MROWS*DDD];                 // ln outputs (reused)
__device__ float g_qkv[MROWS*3*DDD];             // qkv projection
__device__ float g_logits[(size_t)BH*KKK*KKK];   // attn logits / probs (33.5 MB)
__device__ float g_attnout[MROWS*DDD];           // attention output (B,K,D)
__device__ float g_slots2[MROWS*DDD];            // residual after attention
__device__ float g_ffn[MROWS*4*DDD];             // ffn hidden

// ---------- LayerNorm: one block per row (512 elems) ----------
__global__ void __launch_bounds__(128) ln_kernel(
    const float* __restrict__ in, const float* __restrict__ w,
    const float* __restrict__ b, float* __restrict__ out)
{
    const int row = blockIdx.x;
    const int t = threadIdx.x;  // 128
    float4 v = ((const float4*)(in + (size_t)row*DDD))[t];
    float s  = v.x+v.y+v.z+v.w;
    float ss = v.x*v.x+v.y*v.y+v.z*v.z+v.w*v.w;
    #pragma unroll
    for (int o=16;o>0;o>>=1){
        s  += __shfl_xor_sync(0xffffffffu, s,  o);
        ss += __shfl_xor_sync(0xffffffffu, ss, o);
    }
    __shared__ float sm[8];
    const int wid = t>>5, lid = t&31;
    if (lid==0){ sm[wid]=s; sm[4+wid]=ss; }
    __syncthreads();
    s  = sm[0]+sm[1]+sm[2]+sm[3];
    ss = sm[4]+sm[5]+sm[6]+sm[7];
    const float mean = s*(1.0f/DDD);
    const float var  = ss*(1.0f/DDD) - mean*mean;
    const float inv  = rsqrtf(var + 1e-5f);
    float4 wv = ((const float4*)w)[t];
    float4 bv = ((const float4*)b)[t];
    float4 o4;
    o4.x = (v.x-mean)*inv*wv.x + bv.x;
    o4.y = (v.y-mean)*inv*wv.y + bv.y;
    o4.z = (v.z-mean)*inv*wv.z + bv.z;
    o4.w = (v.w-mean)*inv*wv.w + bv.w;
    ((float4*)(out + (size_t)row*DDD))[t] = o4;
}

// ---------- SGEMM: C = A(M,K) @ B(K,N) [+bias][+gelu | +residual] ----------
// BM=128, BK=8; BN/TN templated (128/8 or 64/4), 256 threads, FFMA2 inner loop.
// EPI: 0 = none, 1 = +bias then exact GELU, 2 = +bias then +residual
template<int BN, int TN, int EPI>
__global__ void __launch_bounds__(256) sgemm_kernel(
    int Md, int Nd, int Kd,
    const float* __restrict__ A, const float* __restrict__ Bw,
    const float* __restrict__ bias, const float* __restrict__ Res,
    float* __restrict__ C)
{
    constexpr int BM = 128, BK = 8, TM = 8;
    __shared__ float As[BK][BM];
    __shared__ float Bs[BK][BN];

    const int tid = threadIdx.x;
    const int bx = blockIdx.x, by = blockIdx.y;
    const float* Ab = A  + (size_t)by*BM*Kd;
    const float* Bb = Bw + bx*BN;

    const int arow = tid >> 1;                // 0..127
    const int acol = (tid & 1) * 4;           // 0 or 4
    const int brow = tid >> 5;                // 0..7
    const int bcol = (tid & 31) * (BN/32);    // step 4 or 2

    const int tr = (tid >> 4) * TM;           // 0..120
    const int tc = (tid & 15) * TN;           // 0..BN-TN

    u64 acc[TM][TN/2];
    #pragma unroll
    for (int i=0;i<TM;i++)
        #pragma unroll
        for (int j=0;j<TN/2;j++) acc[i][j] = 0ull;

    for (int k0 = 0; k0 < Kd; k0 += BK){
        float4 av = *(const float4*)(Ab + (size_t)arow*Kd + k0 + acol);
        As[acol+0][arow]=av.x; As[acol+1][arow]=av.y;
        As[acol+2][arow]=av.z; As[acol+3][arow]=av.w;
        if (BN == 128){
            *(float4*)&Bs[brow][bcol] = *(const float4*)(Bb + (size_t)(k0+brow)*Nd + bcol);
        } else {
            *(float2*)&Bs[brow][bcol] = *(const float2*)(Bb + (size_t)(k0+brow)*Nd + bcol);
        }
        __syncthreads();
        #pragma unroll
        for (int kk=0;kk<BK;kk++){
            float4 a0 = *(const float4*)&As[kk][tr];
            float4 a1 = *(const float4*)&As[kk][tr+4];
            u64 ad[TM];
            ad[0]=dup2f(a0.x); ad[1]=dup2f(a0.y); ad[2]=dup2f(a0.z); ad[3]=dup2f(a0.w);
            ad[4]=dup2f(a1.x); ad[5]=dup2f(a1.y); ad[6]=dup2f(a1.z); ad[7]=dup2f(a1.w);
            const u64* bp = (const u64*)&Bs[kk][tc];
            u64 bn[TN/2];
            #pragma unroll
            for (int j=0;j<TN/2;j++) bn[j] = bp[j];
            #pragma unroll
            for (int i=0;i<TM;i++)
                #pragma unroll
                for (int j=0;j<TN/2;j++) ffma2(acc[i][j], ad[i], bn[j]);
        }
        __syncthreads();
    }

    const size_t row0 = (size_t)by*BM + tr;
    const int col0 = bx*BN + tc;
    float bv[TN];
    #pragma unroll
    for (int j=0;j<TN;j++) bv[j] = (EPI != 0) ? bias[col0+j] : 0.0f;

    #pragma unroll
    for (int i=0;i<TM;i++){
        float o[TN];
        #pragma unroll
        for (int j=0;j<TN/2;j++) unpack2f(acc[i][j], o[2*j], o[2*j+1]);
        const size_t r = row0 + i;
        #pragma unroll
        for (int j=0;j<TN;j++){
            float c = o[j] + bv[j];
            if (EPI == 1) c = 0.5f*c*(1.0f + erff(c*0.70710678118654752f));
            if (EPI == 2) c += Res[r*Nd + col0 + j];
            o[j] = c;
        }
        #pragma unroll
        for (int j=0;j<TN;j+=4)
            *(float4*)(C + r*Nd + col0 + j) = make_float4(o[j],o[j+1],o[j+2],o[j+3]);
    }
}

// ---------- Edge bias: logits[b,h,q,k] = edge_b[h] + sum_d pairwise[b,q,k,d]*edge_w[d,h]
// One block per (b,q); 128 threads; each thread owns 4 consecutive k.
// Pairwise rows stream through L1 (each thread consumes its full 512B rows).
__global__ void __launch_bounds__(128) edge_bias_kernel(
    const float* __restrict__ pw, const float* __restrict__ ew,
    const float* __restrict__ eb, float* __restrict__ logits)
{
    __shared__ float ews[DPP*NH];  // 1024 floats, layout [d][h]
    const int q = blockIdx.x;
    const int b = blockIdx.y;
    const int tid = threadIdx.x;   // 128
    ((float4*)ews)[tid]       = ((const float4*)ew)[tid];
    ((float4*)ews)[tid + 128] = ((const float4*)ew)[tid + 128];
    __syncthreads();

    const int k0 = tid*4;
    const float* base = pw + (((size_t)b*KKK + q)*KKK + k0)*DPP;

    u64 acc[4][4];   // [k-sub][head-pair]
    #pragma unroll
    for (int j=0;j<4;j++){
        u64 ini = pack2f(eb[2*j], eb[2*j+1]);
        #pragma unroll
        for (int g=0;g<4;g++) acc[g][j] = ini;
    }

    #pragma unroll 4
    for (int d4=0; d4<32; d4++){
        float4 p[4];
        #pragma unroll
        for (int g=0;g<4;g++)
            p[g] = *(const float4*)(base + (size_t)g*DPP + d4*4);
        #pragma unroll
        for (int x=0;x<4;x++){
            const int d = d4*4 + x;
            const u64* e2 = (const u64*)&ews[d*NH];   // 4 head-pairs
            u64 e0=e2[0], e1=e2[1], e2v=e2[2], e3=e2[3];
            #pragma unroll
            for (int g=0;g<4;g++){
                const float pv = (x==0)?p[g].x : (x==1)?p[g].y : (x==2)?p[g].z : p[g].w;
                u64 pd = dup2f(pv);
                ffma2(acc[g][0], pd, e0);
                ffma2(acc[g][1], pd, e1);
                ffma2(acc[g][2], pd, e2v);
                ffma2(acc[g][3], pd, e3);
            }
        }
    }

    #pragma unroll
    for (int j=0;j<4;j++){
        float x0,y0,x1,y1,x2,y2,x3,y3;
        unpack2f(acc[0][j],x0,y0); unpack2f(acc[1][j],x1,y1);
        unpack2f(acc[2][j],x2,y2); unpack2f(acc[3][j],x3,y3);
        const size_t b0 = (((size_t)(b*NH + 2*j  )*KKK + q)*KKK) + k0;
        const size_t b1 = (((size_t)(b*NH + 2*j+1)*KKK + q)*KKK) + k0;
        *(float4*)(logits + b0) = make_float4(x0,x1,x2,x3);
        *(float4*)(logits + b1) = make_float4(y0,y1,y2,y3);
    }
}

// ---------- QK^T: logits += (1/8) * q . k  (64x64 tiles per (b,h)) ----------
__global__ void __launch_bounds__(256) qk_kernel(
    const float* __restrict__ qkv, float* __restrict__ logits)
{
    __shared__ float Qs[64][64];  // [d][q]
    __shared__ float Ks[64][64];  // [d][k]
    const int bh = blockIdx.z, b = bh >> 3, h = bh & 7;
    const int q0 = blockIdx.y*64, k0 = blockIdx.x*64;
    const int tid = threadIdx.x;
    const float* qb = qkv + ((size_t)(b*KKK) + q0)*(3*DDD) + h*HDIM;
    const float* kb = qkv + ((size_t)(b*KKK) + k0)*(3*DDD) + DDD + h*HDIM;

    // Transposed load: lanes span rows -> conflict-free transposed STS.
    #pragma unroll
    for (int i=0;i<4;i++){
        const int lin = tid + i*256;     // 0..1023 float4 ids
        const int r = lin & 63;
        const int c4 = (lin >> 6) * 4;
        float4 v = *(const float4*)(qb + (size_t)r*(3*DDD) + c4);
        Qs[c4+0][r]=v.x; Qs[c4+1][r]=v.y; Qs[c4+2][r]=v.z; Qs[c4+3][r]=v.w;
        float4 u = *(const float4*)(kb + (size_t)r*(3*DDD) + c4);
        Ks[c4+0][r]=u.x; Ks[c4+1][r]=u.y; Ks[c4+2][r]=u.z; Ks[c4+3][r]=u.w;
    }
    __syncthreads();

    const int tr = (tid>>4)*4, tc = (tid&15)*4;
    u64 acc[4][2];
    #pragma unroll
    for (int i=0;i<4;i++){ acc[i][0]=0ull; acc[i][1]=0ull; }

    #pragma unroll
    for (int d=0; d<64; d++){
        float4 a = *(const float4*)&Qs[d][tr];
        u64 a0=dup2f(a.x), a1=dup2f(a.y), a2=dup2f(a.z), a3=dup2f(a.w);
        const u64* bp = (const u64*)&Ks[d][tc];
        u64 b0=bp[0], b1=bp[1];
        ffma2(acc[0][0],a0,b0); ffma2(acc[0][1],a0,b1);
        ffma2(acc[1][0],a1,b0); ffma2(acc[1][1],a1,b1);
        ffma2(acc[2][0],a2,b0); ffma2(acc[2][1],a2,b1);
        ffma2(acc[3][0],a3,b0); ffma2(acc[3][1],a3,b1);
    }

    float* lp = logits + ((size_t)bh*KKK + q0)*KKK + k0;
    #pragma unroll
    for (int i=0;i<4;i++){
        float4* p = (float4*)(lp + (size_t)(tr+i)*KKK + tc);
        float4 old = *p;
        float x0,x1,x2,x3;
        unpack2f(acc[i][0], x0, x1);
        unpack2f(acc[i][1], x2, x3);
        old.x += 0.125f*x0; old.y += 0.125f*x1;
        old.z += 0.125f*x2; old.w += 0.125f*x3;
        *p = old;
    }
}

// ---------- Softmax over last dim (512) of logits ----------
__global__ void __launch_bounds__(128) softmax_kernel(float* __restrict__ logits)
{
    const size_t row = blockIdx.x;
    float* p = logits + row*KKK;
    const int t = threadIdx.x;
    float4 v = ((float4*)p)[t];
    float m = fmaxf(fmaxf(v.x,v.y), fmaxf(v.z,v.w));
    #pragma unroll
    for (int o=16;o>0;o>>=1) m = fmaxf(m, __shfl_xor_sync(0xffffffffu,m,o));
    __shared__ float smx[4], sms[4];
    const int wid=t>>5, lid=t&31;
    if (lid==0) smx[wid]=m;
    __syncthreads();
    m = fmaxf(fmaxf(smx[0],smx[1]), fmaxf(smx[2],smx[3]));
    v.x = expf(v.x-m); v.y = expf(v.y-m); v.z = expf(v.z-m); v.w = expf(v.w-m);
    float s = v.x+v.y+v.z+v.w;
    #pragma unroll
    for (int o=16;o>0;o>>=1) s += __shfl_xor_sync(0xffffffffu,s,o);
    if (lid==0) sms[wid]=s;
    __syncthreads();
    s = sms[0]+sms[1]+sms[2]+sms[3];
    const float r = 1.0f/s;
    v.x*=r; v.y*=r; v.z*=r; v.w*=r;
    ((float4*)p)[t] = v;
}

// ---------- AV: attnout[b,q,h*64+d] = sum_k attn[b,h,q,k] * v[b,k,h,d] ----------
__global__ void __launch_bounds__(256) av_kernel(
    const float* __restrict__ logits, const float* __restrict__ qkv,
    float* __restrict__ out)
{
    __shared__ float Asm[64][64];  // [k][q]
    __shared__ float Vs[64][64];   // [k][d]
    const int bh = blockIdx.y, b = bh >> 3, h = bh & 7;
    const int q0 = blockIdx.x*64;
    const int tid = threadIdx.x;
    const float* ab = logits + ((size_t)bh*KKK + q0)*KKK;
    const float* vb = qkv + (size_t)(b*KKK)*(3*DDD) + 2*DDD + h*HDIM;
    const int tr = (tid>>4)*4, tc = (tid&15)*4;

    u64 acc[4][2];
    #pragma unroll
    for (int i=0;i<4;i++){ acc[i][0]=0ull; acc[i][1]=0ull; }

    for (int k0=0; k0<KKK; k0+=64){
        #pragma unroll
        for (int i=0;i<4;i++){
            const int lin = tid + i*256;
            const int r  = lin & 63;          // q
            const int c4 = (lin >> 6) * 4;    // k-in-tile
            float4 v = *(const float4*)(ab + (size_t)r*KKK + k0 + c4);
            Asm[c4+0][r]=v.x; Asm[c4+1][r]=v.y; Asm[c4+2][r]=v.z; Asm[c4+3][r]=v.w;
            const int rv = lin >> 4;          // k row
            const int cv = (lin & 15) * 4;    // d
            *(float4*)&Vs[rv][cv] = *(const float4*)(vb + (size_t)(k0+rv)*(3*DDD) + cv);
        }
        __syncthreads();
        #pragma unroll
        for (int kk=0;kk<64;kk++){
            float4 a = *(const float4*)&Asm[kk][tr];
            u64 a0=dup2f(a.x), a1=dup2f(a.y), a2=dup2f(a.z), a3=dup2f(a.w);
            const u64* bp = (const u64*)&Vs[kk][tc];
            u64 b0=bp[0], b1=bp[1];
            ffma2(acc[0][0],a0,b0); ffma2(acc[0][1],a0,b1);
            ffma2(acc[1][0],a1,b0); ffma2(acc[1][1],a1,b1);
            ffma2(acc[2][0],a2,b0); ffma2(acc[2][1],a2,b1);
            ffma2(acc[3][0],a3,b0); ffma2(acc[3][1],a3,b1);
        }
        __syncthreads();
    }

    #pragma unroll
    for (int i=0;i<4;i++){
        float x0,x1,x2,x3;
        unpack2f(acc[i][0], x0, x1);
        unpack2f(acc[i][1], x2, x3);
        *(float4*)(out + (size_t)(b*KKK + q0 + tr + i)*DDD + h*HDIM + tc)
            = make_float4(x0,x1,x2,x3);
    }
}

// ---------- host launch ----------
extern "C" void kernel_launch(void* const* d_in, const int* in_sizes, int n_in,
                              void* d_out, int out_size)
{
    const float* slots    = (const float*)d_in[0];
    const float* pairwise = (const float*)d_in[1];
    const float* ln1w     = (const float*)d_in[2];
    const float* ln1b     = (const float*)d_in[3];
    const float* ln2w     = (const float*)d_in[4];
    const float* ln2b     = (const float*)d_in[5];
    const float* wqkv     = (const float*)d_in[6];
    const float* edge_w   = (const float*)d_in[7];
    const float* edge_b   = (const float*)d_in[8];
    const float* out_w    = (const float*)d_in[9];
    const float* out_b    = (const float*)d_in[10];
    const float* ffn_w1   = (const float*)d_in[11];
    const float* ffn_b1   = (const float*)d_in[12];
    const float* ffn_w2   = (const float*)d_in[13];
    const float* ffn_b2   = (const float*)d_in[14];
    float* out = (float*)d_out;

    float *x_, *qkv_, *log_, *ao_, *s2_, *ffn_;
    cudaGetSymbolAddress((void**)&x_,   g_x);
    cudaGetSymbolAddress((void**)&qkv_, g_qkv);
    cudaGetSymbolAddress((void**)&log_, g_logits);
    cudaGetSymbolAddress((void**)&ao_,  g_attnout);
    cudaGetSymbolAddress((void**)&s2_,  g_slots2);
    cudaGetSymbolAddress((void**)&ffn_, g_ffn);

    // 1) LN1
    ln_kernel<<<MROWS,128>>>(slots, ln1w, ln1b, x_);
    // 2) QKV projection (2048 x 1536 x 512)
    sgemm_kernel<128,8,0><<<dim3(3*DDD/128, MROWS/128), 256>>>(
        MROWS, 3*DDD, DDD, x_, wqkv, nullptr, nullptr, qkv_);
    // 3) edge bias -> logits
    edge_bias_kernel<<<dim3(KKK,BB),128>>>(pairwise, edge_w, edge_b, log_);
    // 4) logits += scale * QK^T
    qk_kernel<<<dim3(KKK/64, KKK/64, BH), 256>>>(qkv_, log_);
    // 5) softmax
    softmax_kernel<<<BH*KKK,128>>>(log_);
    // 6) attn @ V -> (B,K,D)
    av_kernel<<<dim3(KKK/64, BH), 256>>>(log_, qkv_, ao_);
    // 7) out projection + residual (2048 x 512 x 512)
    sgemm_kernel<64,4,2><<<dim3(DDD/64, MROWS/128), 256>>>(
        MROWS, DDD, DDD, ao_, out_w, out_b, slots, s2_);
    // 8) LN2
    ln_kernel<<<MROWS,128>>>(s2_, ln2w, ln2b, x_);
    // 9) FFN1 + exact GELU (2048 x 2048 x 512)
    sgemm_kernel<128,8,1><<<dim3(4*DDD/128, MROWS/128), 256>>>(
        MROWS, 4*DDD, DDD, x_, ffn_w1, ffn_b1, nullptr, ffn_);
    // 10) FFN2 + residual (2048 x 512 x 2048) -> final output
    sgemm_kernel<64,4,2><<<dim3(DDD/64, MROWS/128), 256>>>(
        MROWS, DDD, 4*DDD, ffn_, ffn_w2, ffn_b2, s2_, out);
}

// round 7
// speedup vs baseline: 1.6621x; 1.6621x over previous
#include <cuda_runtime.h>
#include <math.h>

// Problem constants
#define BB 4
#define KKK 512          // slots per batch
#define DDD 512          // slot dim
#define DPP 128          // pairwise dim
#define NH 8             // heads
#define HDIM 64          // head dim
#define MROWS (BB*KKK)   // 2048
#define BH (BB*NH)       // 32

typedef unsigned u32;
typedef unsigned long long u64;

// ---------- packed fp32x2 helpers (edge bias kernel) ----------
__device__ __forceinline__ u64 dup2f(float x){
    u64 r; unsigned xi = __float_as_uint(x);
    asm("mov.b64 %0, {%1,%1};" : "=l"(r) : "r"(xi));
    return r;
}
__device__ __forceinline__ u64 pack2f(float x, float y){
    u64 r;
    asm("mov.b64 %0, {%1,%2};" : "=l"(r) : "r"(__float_as_uint(x)), "r"(__float_as_uint(y)));
    return r;
}
__device__ __forceinline__ void unpack2f(u64 v, float &x, float &y){
    unsigned a,b;
    asm("mov.b64 {%0,%1}, %2;" : "=r"(a), "=r"(b) : "l"(v));
    x = __uint_as_float(a); y = __uint_as_float(b);
}
__device__ __forceinline__ void ffma2(u64 &d, u64 a, u64 b){
    asm("fma.rn.f32x2 %0, %1, %2, %0;" : "+l"(d) : "l"(a), "l"(b));
}

// ---------- tf32 MMA helpers ----------
__device__ __forceinline__ float to_tf32(float x){
    float r; asm("cvt.rna.tf32.f32 %0, %1;" : "=f"(r) : "f"(x)); return r;
}
__device__ __forceinline__ float4 cvt4(float4 v){
    v.x = to_tf32(v.x); v.y = to_tf32(v.y);
    v.z = to_tf32(v.z); v.w = to_tf32(v.w);
    return v;
}
__device__ __forceinline__ void mma8(float* c, const u32* a, const u32* b){
    asm("mma.sync.aligned.m16n8k8.row.col.f32.tf32.tf32.f32 "
        "{%0,%1,%2,%3}, {%4,%5,%6,%7}, {%8,%9}, {%0,%1,%2,%3};"
        : "+f"(c[0]), "+f"(c[1]), "+f"(c[2]), "+f"(c[3])
        : "r"(a[0]), "r"(a[1]), "r"(a[2]), "r"(a[3]),
          "r"(b[0]), "r"(b[1]));
}

// ---------- scratch (no dynamic allocation allowed) ----------
__device__ float g_x[MROWS*DDD];
__device__ float g_qkv[MROWS*3*DDD];
__device__ float g_logits[(size_t)BH*KKK*KKK];   // 33.5 MB
__device__ float g_attnout[MROWS*DDD];
__device__ float g_slots2[MROWS*DDD];
__device__ float g_ffn[MROWS*4*DDD];

// =====================================================================
// mma_core: C(128 x BN) += A(128 x Ktot) * B(Ktot x BN), tf32 tensor path
//   A row-major (lda), staged to As[m][20]        (stride 20, conflict-free)
//   B:
//     BNK=false: global row-major K x N (weights)  -> Bs[k][BN+8]
//     BNK=true : global row-major N x K (K-slots)  -> Bs[n][20] (no transpose)
//   256 threads = 8 warps (4 m-rows x 2 n-cols), warp tile 32 x (BN/2).
//   Register-prefetch pipeline over single smem buffer.
// =====================================================================
template<int BN, bool BNK>
__device__ __forceinline__ void mma_core(
    const float* __restrict__ A, int lda,
    const float* __restrict__ B, int ldb,
    int Ktot, float* smem, float (&acc)[2][BN/16][4])
{
    constexpr int NF = BN/16;
    constexpr int SB = BN + 8;       // 136 or 72; both ≡ 8 (mod 32)
    constexpr int BITER = BN/64;     // B-loader iterations (2 or 1)
    float* As = smem;                // 128*20 floats
    float* Bs = smem + 128*20;

    const int tid  = threadIdx.x;
    const int warp = tid >> 5, lane = tid & 31;
    const int wr = warp & 3, wc = warp >> 2;
    const int g = lane >> 2, t = lane & 3;
    const int mw = wr * 32, nw = wc * (BN/2);

    // A loader mapping: 128x16 tile, 512 float4, 2 per thread
    const int ar0 = tid >> 2,  ac0 = (tid & 3) * 4;
    const int ar1 = (tid+256) >> 2, ac1 = ((tid+256) & 3) * 4;

    float4 pa0, pa1, pb0, pb1;

    // prologue: fetch tile 0
    pa0 = cvt4(*(const float4*)(A + (size_t)ar0*lda + ac0));
    pa1 = cvt4(*(const float4*)(A + (size_t)ar1*lda + ac1));
    if (BNK){
        pb0 = cvt4(*(const float4*)(B + (size_t)ar0*ldb + ac0));
        if (BITER == 2)
            pb1 = cvt4(*(const float4*)(B + (size_t)ar1*ldb + ac1));
    } else {
        const int br = tid / (BN/4), bc = (tid % (BN/4)) * 4;
        pb0 = cvt4(*(const float4*)(B + (size_t)br*ldb + bc));
        if (BITER == 2){
            const int br2 = (tid+256) / (BN/4), bc2 = ((tid+256) % (BN/4)) * 4;
            pb1 = cvt4(*(const float4*)(B + (size_t)br2*ldb + bc2));
        }
    }
    // store tile 0
    *(float4*)(As + ar0*20 + ac0) = pa0;
    *(float4*)(As + ar1*20 + ac1) = pa1;
    if (BNK){
        *(float4*)(Bs + ar0*20 + ac0) = pb0;
        if (BITER == 2) *(float4*)(Bs + ar1*20 + ac1) = pb1;
    } else {
        const int br = tid / (BN/4), bc = (tid % (BN/4)) * 4;
        *(float4*)(Bs + br*SB + bc) = pb0;
        if (BITER == 2){
            const int br2 = (tid+256) / (BN/4), bc2 = ((tid+256) % (BN/4)) * 4;
            *(float4*)(Bs + br2*SB + bc2) = pb1;
        }
    }
    __syncthreads();

    for (int k0 = 0; k0 < Ktot; k0 += 16){
        const bool notlast = (k0 + 16 < Ktot);
        // prefetch next tile into registers
        if (notlast){
            const int kn = k0 + 16;
            pa0 = cvt4(*(const float4*)(A + (size_t)ar0*lda + kn + ac0));
            pa1 = cvt4(*(const float4*)(A + (size_t)ar1*lda + kn + ac1));
            if (BNK){
                pb0 = cvt4(*(const float4*)(B + (size_t)ar0*ldb + kn + ac0));
                if (BITER == 2)
                    pb1 = cvt4(*(const float4*)(B + (size_t)ar1*ldb + kn + ac1));
            } else {
                const int br = tid / (BN/4), bc = (tid % (BN/4)) * 4;
                pb0 = cvt4(*(const float4*)(B + (size_t)(kn+br)*ldb + bc));
                if (BITER == 2){
                    const int br2 = (tid+256) / (BN/4), bc2 = ((tid+256) % (BN/4)) * 4;
                    pb1 = cvt4(*(const float4*)(B + (size_t)(kn+br2)*ldb + bc2));
                }
            }
        }
        // compute on current smem tile
        #pragma unroll
        for (int ks = 0; ks < 2; ks++){
            const int kk = ks * 8;
            u32 af[2][4];
            #pragma unroll
            for (int mf = 0; mf < 2; mf++){
                const int mb = mw + mf*16;
                af[mf][0] = __float_as_uint(As[(mb+g)*20   + kk + t]);
                af[mf][1] = __float_as_uint(As[(mb+8+g)*20 + kk + t]);
                af[mf][2] = __float_as_uint(As[(mb+g)*20   + kk + 4 + t]);
                af[mf][3] = __float_as_uint(As[(mb+8+g)*20 + kk + 4 + t]);
            }
            u32 bf[NF][2];
            #pragma unroll
            for (int nf = 0; nf < NF; nf++){
                const int nb = nw + nf*8;
                if (BNK){
                    bf[nf][0] = __float_as_uint(Bs[(nb+g)*20 + kk + t]);
                    bf[nf][1] = __float_as_uint(Bs[(nb+g)*20 + kk + 4 + t]);
                } else {
                    bf[nf][0] = __float_as_uint(Bs[(kk+t)*SB   + nb + g]);
                    bf[nf][1] = __float_as_uint(Bs[(kk+4+t)*SB + nb + g]);
                }
            }
            #pragma unroll
            for (int mf = 0; mf < 2; mf++)
                #pragma unroll
                for (int nf = 0; nf < NF; nf++)
                    mma8(acc[mf][nf], af[mf], bf[nf]);
        }
        __syncthreads();
        if (notlast){
            *(float4*)(As + ar0*20 + ac0) = pa0;
            *(float4*)(As + ar1*20 + ac1) = pa1;
            if (BNK){
                *(float4*)(Bs + ar0*20 + ac0) = pb0;
                if (BITER == 2) *(float4*)(Bs + ar1*20 + ac1) = pb1;
            } else {
                const int br = tid / (BN/4), bc = (tid % (BN/4)) * 4;
                *(float4*)(Bs + br*SB + bc) = pb0;
                if (BITER == 2){
                    const int br2 = (tid+256) / (BN/4), bc2 = ((tid+256) % (BN/4)) * 4;
                    *(float4*)(Bs + br2*SB + bc2) = pb1;
                }
            }
            __syncthreads();
        }
    }
}

// ---------- projection GEMM + fused epilogues ----------
// EPI: 0 = none, 1 = +bias then exact GELU, 2 = +bias then +residual
template<int BN, int EPI>
__global__ void __launch_bounds__(256) mma_proj(
    const float* __restrict__ A, const float* __restrict__ Bw,
    const float* __restrict__ bias, const float* __restrict__ Res,
    float* __restrict__ C, int lda, int N, int Ktot)
{
    __shared__ float smem[128*20 + 16*(BN+8)];
    const float* Ab = A  + (size_t)blockIdx.y*128*lda;
    const float* Bb = Bw + blockIdx.x*BN;
    float acc[2][BN/16][4] = {};
    mma_core<BN,false>(Ab, lda, Bb, N, Ktot, smem, acc);

    const int tid  = threadIdx.x;
    const int warp = tid >> 5, lane = tid & 31;
    const int wr = warp & 3, wc = warp >> 2;
    const int g = lane >> 2, t = lane & 3;
    const size_t row0 = (size_t)blockIdx.y*128 + wr*32;
    const int col0 = blockIdx.x*BN + wc*(BN/2);

    #pragma unroll
    for (int mf = 0; mf < 2; mf++){
        #pragma unroll
        for (int nf = 0; nf < BN/16; nf++){
            const int col = col0 + nf*8 + t*2;
            float b0 = 0.f, b1 = 0.f;
            if (EPI != 0){ b0 = bias[col]; b1 = bias[col+1]; }
            #pragma unroll
            for (int half = 0; half < 2; half++){
                const size_t r = row0 + mf*16 + g + half*8;
                float v0 = acc[mf][nf][half*2]   + b0;
                float v1 = acc[mf][nf][half*2+1] + b1;
                if (EPI == 1){
                    v0 = 0.5f*v0*(1.0f + erff(v0*0.70710678118654752f));
                    v1 = 0.5f*v1*(1.0f + erff(v1*0.70710678118654752f));
                }
                if (EPI == 2){
                    float2 rr = *(const float2*)(Res + r*(size_t)N + col);
                    v0 += rr.x; v1 += rr.y;
                }
                *(float2*)(C + r*(size_t)N + col) = make_float2(v0, v1);
            }
        }
    }
}

// ---------- QK^T via tensor cores: logits += 0.125 * Q K^T ----------
__global__ void __launch_bounds__(256) mma_qk(
    const float* __restrict__ qkv, float* __restrict__ logits)
{
    __shared__ float smem[128*20 + 128*20];
    const int z = blockIdx.z, b = z >> 3, h = z & 7;
    const float* Aq = qkv + ((size_t)(b*KKK) + blockIdx.y*128)*(3*DDD) + h*HDIM;
    const float* Bk = qkv + ((size_t)(b*KKK) + blockIdx.x*128)*(3*DDD) + DDD + h*HDIM;
    float acc[2][8][4] = {};
    mma_core<128,true>(Aq, 3*DDD, Bk, 3*DDD, HDIM, smem, acc);

    float* Cb = logits + ((size_t)z*KKK + blockIdx.y*128)*KKK + blockIdx.x*128;
    const int tid  = threadIdx.x;
    const int warp = tid >> 5, lane = tid & 31;
    const int wr = warp & 3, wc = warp >> 2;
    const int g = lane >> 2, t = lane & 3;
    const int r0 = wr*32, c0 = wc*64;

    #pragma unroll
    for (int mf = 0; mf < 2; mf++){
        #pragma unroll
        for (int nf = 0; nf < 8; nf++){
            const int col = c0 + nf*8 + t*2;
            #pragma unroll
            for (int half = 0; half < 2; half++){
                const int r = r0 + mf*16 + g + half*8;
                float2* p = (float2*)(Cb + (size_t)r*KKK + col);
                float2 o = *p;
                o.x += 0.125f*acc[mf][nf][half*2];
                o.y += 0.125f*acc[mf][nf][half*2+1];
                *p = o;
            }
        }
    }
}

// ---------- AV via tensor cores: out[b,q,h*64+d] = P @ V ----------
__global__ void __launch_bounds__(256) mma_av(
    const float* __restrict__ logits, const float* __restrict__ qkv,
    float* __restrict__ out)
{
    __shared__ float smem[128*20 + 16*72];
    const int z = blockIdx.z, b = z >> 3, h = z & 7;
    const float* Ap = logits + ((size_t)z*KKK + blockIdx.y*128)*KKK;
    const float* Bv = qkv + (size_t)(b*KKK)*(3*DDD) + 2*DDD + h*HDIM;
    float acc[2][4][4] = {};
    mma_core<64,false>(Ap, KKK, Bv, 3*DDD, KKK, smem, acc);

    float* Cb = out + ((size_t)(b*KKK) + blockIdx.y*128)*DDD + h*HDIM;
    const int tid  = threadIdx.x;
    const int warp = tid >> 5, lane = tid & 31;
    const int wr = warp & 3, wc = warp >> 2;
    const int g = lane >> 2, t = lane & 3;
    const int r0 = wr*32, c0 = wc*32;

    #pragma unroll
    for (int mf = 0; mf < 2; mf++){
        #pragma unroll
        for (int nf = 0; nf < 4; nf++){
            const int col = c0 + nf*8 + t*2;
            #pragma unroll
            for (int half = 0; half < 2; half++){
                const int r = r0 + mf*16 + g + half*8;
                *(float2*)(Cb + (size_t)r*DDD + col) =
                    make_float2(acc[mf][nf][half*2], acc[mf][nf][half*2+1]);
            }
        }
    }
}

// ---------- LayerNorm: one block per row (512 elems) ----------
__global__ void __launch_bounds__(128) ln_kernel(
    const float* __restrict__ in, const float* __restrict__ w,
    const float* __restrict__ b, float* __restrict__ out)
{
    const int row = blockIdx.x;
    const int t = threadIdx.x;  // 128
    float4 v = ((const float4*)(in + (size_t)row*DDD))[t];
    float s  = v.x+v.y+v.z+v.w;
    float ss = v.x*v.x+v.y*v.y+v.z*v.z+v.w*v.w;
    #pragma unroll
    for (int o=16;o>0;o>>=1){
        s  += __shfl_xor_sync(0xffffffffu, s,  o);
        ss += __shfl_xor_sync(0xffffffffu, ss, o);
    }
    __shared__ float sm[8];
    const int wid = t>>5, lid = t&31;
    if (lid==0){ sm[wid]=s; sm[4+wid]=ss; }
    __syncthreads();
    s  = sm[0]+sm[1]+sm[2]+sm[3];
    ss = sm[4]+sm[5]+sm[6]+sm[7];
    const float mean = s*(1.0f/DDD);
    const float var  = ss*(1.0f/DDD) - mean*mean;
    const float inv  = rsqrtf(var + 1e-5f);
    float4 wv = ((const float4*)w)[t];
    float4 bv = ((const float4*)b)[t];
    float4 o4;
    o4.x = (v.x-mean)*inv*wv.x + bv.x;
    o4.y = (v.y-mean)*inv*wv.y + bv.y;
    o4.z = (v.z-mean)*inv*wv.z + bv.z;
    o4.w = (v.w-mean)*inv*wv.w + bv.w;
    ((float4*)(out + (size_t)row*DDD))[t] = o4;
}

// ---------- Edge bias (HBM-bound): logits = edge_b + pairwise @ edge_w ----------
__global__ void __launch_bounds__(128) edge_bias_kernel(
    const float* __restrict__ pw, const float* __restrict__ ew,
    const float* __restrict__ eb, float* __restrict__ logits)
{
    __shared__ float ews[DPP*NH];  // [d][h]
    const int q = blockIdx.x;
    const int b = blockIdx.y;
    const int tid = threadIdx.x;   // 128
    ((float4*)ews)[tid]       = ((const float4*)ew)[tid];
    ((float4*)ews)[tid + 128] = ((const float4*)ew)[tid + 128];
    __syncthreads();

    const int k0 = tid*4;
    const float* base = pw + (((size_t)b*KKK + q)*KKK + k0)*DPP;

    u64 acc[4][4];   // [k-sub][head-pair]
    #pragma unroll
    for (int j=0;j<4;j++){
        u64 ini = pack2f(eb[2*j], eb[2*j+1]);
        #pragma unroll
        for (int g=0;g<4;g++) acc[g][j] = ini;
    }

    #pragma unroll 4
    for (int d4=0; d4<32; d4++){
        float4 p[4];
        #pragma unroll
        for (int g=0;g<4;g++)
            p[g] = *(const float4*)(base + (size_t)g*DPP + d4*4);
        #pragma unroll
        for (int x=0;x<4;x++){
            const int d = d4*4 + x;
            const u64* e2 = (const u64*)&ews[d*NH];
            u64 e0=e2[0], e1=e2[1], e2v=e2[2], e3=e2[3];
            #pragma unroll
            for (int g=0;g<4;g++){
                const float pv = (x==0)?p[g].x : (x==1)?p[g].y : (x==2)?p[g].z : p[g].w;
                u64 pd = dup2f(pv);
                ffma2(acc[g][0], pd, e0);
                ffma2(acc[g][1], pd, e1);
                ffma2(acc[g][2], pd, e2v);
                ffma2(acc[g][3], pd, e3);
            }
        }
    }

    #pragma unroll
    for (int j=0;j<4;j++){
        float x0,y0,x1,y1,x2,y2,x3,y3;
        unpack2f(acc[0][j],x0,y0); unpack2f(acc[1][j],x1,y1);
        unpack2f(acc[2][j],x2,y2); unpack2f(acc[3][j],x3,y3);
        const size_t b0 = (((size_t)(b*NH + 2*j  )*KKK + q)*KKK) + k0;
        const size_t b1 = (((size_t)(b*NH + 2*j+1)*KKK + q)*KKK) + k0;
        *(float4*)(logits + b0) = make_float4(x0,x1,x2,x3);
        *(float4*)(logits + b1) = make_float4(y0,y1,y2,y3);
    }
}

// ---------- Softmax over last dim (512) ----------
__global__ void __launch_bounds__(128) softmax_kernel(float* __restrict__ logits)
{
    const size_t row = blockIdx.x;
    float* p = logits + row*KKK;
    const int t = threadIdx.x;
    float4 v = ((float4*)p)[t];
    float m = fmaxf(fmaxf(v.x,v.y), fmaxf(v.z,v.w));
    #pragma unroll
    for (int o=16;o>0;o>>=1) m = fmaxf(m, __shfl_xor_sync(0xffffffffu,m,o));
    __shared__ float smx[4], sms[4];
    const int wid=t>>5, lid=t&31;
    if (lid==0) smx[wid]=m;
    __syncthreads();
    m = fmaxf(fmaxf(smx[0],smx[1]), fmaxf(smx[2],smx[3]));
    v.x = expf(v.x-m); v.y = expf(v.y-m); v.z = expf(v.z-m); v.w = expf(v.w-m);
    float s = v.x+v.y+v.z+v.w;
    #pragma unroll
    for (int o=16;o>0;o>>=1) s += __shfl_xor_sync(0xffffffffu,s,o);
    if (lid==0) sms[wid]=s;
    __syncthreads();
    s = sms[0]+sms[1]+sms[2]+sms[3];
    const float r = 1.0f/s;
    v.x*=r; v.y*=r; v.z*=r; v.w*=r;
    ((float4*)p)[t] = v;
}

// ---------- host launch ----------
extern "C" void kernel_launch(void* const* d_in, const int* in_sizes, int n_in,
                              void* d_out, int out_size)
{
    const float* slots    = (const float*)d_in[0];
    const float* pairwise = (const float*)d_in[1];
    const float* ln1w     = (const float*)d_in[2];
    const float* ln1b     = (const float*)d_in[3];
    const float* ln2w     = (const float*)d_in[4];
    const float* ln2b     = (const float*)d_in[5];
    const float* wqkv     = (const float*)d_in[6];
    const float* edge_w   = (const float*)d_in[7];
    const float* edge_b   = (const float*)d_in[8];
    const float* out_w    = (const float*)d_in[9];
    const float* out_b    = (const float*)d_in[10];
    const float* ffn_w1   = (const float*)d_in[11];
    const float* ffn_b1   = (const float*)d_in[12];
    const float* ffn_w2   = (const float*)d_in[13];
    const float* ffn_b2   = (const float*)d_in[14];
    float* out = (float*)d_out;

    float *x_, *qkv_, *log_, *ao_, *s2_, *ffn_;
    cudaGetSymbolAddress((void**)&x_,   g_x);
    cudaGetSymbolAddress((void**)&qkv_, g_qkv);
    cudaGetSymbolAddress((void**)&log_, g_logits);
    cudaGetSymbolAddress((void**)&ao_,  g_attnout);
    cudaGetSymbolAddress((void**)&s2_,  g_slots2);
    cudaGetSymbolAddress((void**)&ffn_, g_ffn);

    // 1) LN1
    ln_kernel<<<MROWS,128>>>(slots, ln1w, ln1b, x_);
    // 2) QKV projection (2048 x 1536 x 512), tf32 tensor cores
    mma_proj<128,0><<<dim3(3*DDD/128, MROWS/128), 256>>>(
        x_, wqkv, nullptr, nullptr, qkv_, DDD, 3*DDD, DDD);
    // 3) edge bias -> logits
    edge_bias_kernel<<<dim3(KKK,BB),128>>>(pairwise, edge_w, edge_b, log_);
    // 4) logits += 0.125 * QK^T  (tensor cores)
    mma_qk<<<dim3(KKK/128, KKK/128, BH), 256>>>(qkv_, log_);
    // 5) softmax
    softmax_kernel<<<BH*KKK,128>>>(log_);
    // 6) attn @ V -> (B,K,D)  (tensor cores)
    mma_av<<<dim3(1, KKK/128, BH), 256>>>(log_, qkv_, ao_);
    // 7) out projection + residual (2048 x 512 x 512)
    mma_proj<64,2><<<dim3(DDD/64, MROWS/128), 256>>>(
        ao_, out_w, out_b, slots, s2_, DDD, DDD, DDD);
    // 8) LN2
    ln_kernel<<<MROWS,128>>>(s2_, ln2w, ln2b, x_);
    // 9) FFN1 + exact GELU (2048 x 2048 x 512)
    mma_proj<128,1><<<dim3(4*DDD/128, MROWS/128), 256>>>(
        x_, ffn_w1, ffn_b1, nullptr, ffn_, DDD, 4*DDD, DDD);
    // 10) FFN2 + residual (2048 x 512 x 2048) -> final output
    mma_proj<64,2><<<dim3(DDD/64, MROWS/128), 256>>>(
        ffn_, ffn_w2, ffn_b2, s2_, out, 4*DDD, DDD, 4*DDD);
}